// round 3
// baseline (speedup 1.0000x reference)
#include <cuda_runtime.h>
#include <cuda_bf16.h>
#include <cstdint>

#define NSEQ 16384

// device-global scratch (no allocations allowed)
__device__ __nv_bfloat16 g_Wh[4096 * 64];   // [ki][j] bf16 hi
__device__ __nv_bfloat16 g_Wl[4096 * 64];   // [ki][j] bf16 residual
__device__ float g_bias[4096];              // [ki]

// smem byte offsets
#define SM_WH    0        // W hi  [128 n][64 j] bf16, swizzled 128B rows  (16384)
#define SM_WL    16384    // W lo                                          (16384)
#define SM_BIAS  32768    // 128 f32                                       (512)
#define SM_X     33280    // X hi [128 m][64 j] bf16 swizzled (16384); XL at +16384
                          // epilogue f32 [128][128] swizzled 512B rows overlays here (65536)
#define SM_XL    (SM_X + 16384)
#define SM_TOTAL (SM_X + 65536)   // 98816

__device__ __forceinline__ uint32_t smem_u32(const void *p) {
    uint32_t a;
    asm("{ .reg .u64 t; cvta.to.shared.u64 t, %1; cvt.u32.u64 %0, t; }" : "=r"(a) : "l"(p));
    return a;
}
__device__ __forceinline__ void ldsm4(uint32_t *r, uint32_t a) {
    asm volatile("ldmatrix.sync.aligned.m8n8.x4.shared.b16 {%0,%1,%2,%3}, [%4];"
                 : "=r"(r[0]), "=r"(r[1]), "=r"(r[2]), "=r"(r[3]) : "r"(a));
}
__device__ __forceinline__ void mma16816(float *c, const uint32_t *a, uint32_t b0, uint32_t b1) {
    asm volatile("mma.sync.aligned.m16n8k16.row.col.f32.bf16.bf16.f32 "
                 "{%0,%1,%2,%3}, {%4,%5,%6,%7}, {%8,%9}, {%0,%1,%2,%3};"
                 : "+f"(c[0]), "+f"(c[1]), "+f"(c[2]), "+f"(c[3])
                 : "r"(a[0]), "r"(a[1]), "r"(a[2]), "r"(a[3]), "r"(b0), "r"(b1));
}

// ---------------------------------------------------------------------------
// Prep: bf16 hi/lo split of Wx -> g_Wh/g_Wl [ki][j]; bias[ki] = cm[k] . Wcm[k][i]
// ---------------------------------------------------------------------------
__global__ void prep_kernel(const float *__restrict__ W, const float *__restrict__ cm) {
    const int k = blockIdx.x, tid = threadIdx.x;
    const float *Wk = W + k * 64 * 128;
#pragma unroll
    for (int t = 0; t < 16; ++t) {
        int e = tid + t * 256;          // (i, j)
        int i = e >> 6, j = e & 63;
        float w = Wk[i * 128 + j];
        __nv_bfloat16 h = __float2bfloat16_rn(w);
        g_Wh[(k * 64 + i) * 64 + j] = h;
        g_Wl[(k * 64 + i) * 64 + j] = __float2bfloat16_rn(w - __bfloat162float(h));
    }
    if (tid < 64) {
        const int i = tid;
        const float *cmk = cm + k * 64;
        float s = 0.f;
#pragma unroll 8
        for (int j = 0; j < 64; ++j)
            s = fmaf(cmk[j], Wk[i * 128 + 64 + j], s);
        g_bias[k * 64 + i] = s;
    }
}

// ---------------------------------------------------------------------------
// Main: CTA tile 128m x 128n, K=64. 8 warps as 4m x 2n grid (warp = 32m x 64n).
// 3-pass bf16 split mma. Warp's 64n = one i-group -> shfl L1-normalize.
// Epilogue staged in swizzled smem -> coalesced float4 stores.
// ---------------------------------------------------------------------------
__global__ __launch_bounds__(256, 2)
void mma_kernel(const float *__restrict__ x, float *__restrict__ out) {
    extern __shared__ char smem[];
    const uint32_t sb = smem_u32(smem);
    const int tid = threadIdx.x;
    const int lane = tid & 31, wid = tid >> 5;
    const int wm = wid & 3, wn = wid >> 2;
    const int kib = blockIdx.x;          // 0..31 n-tile (128 ki)
    const int grp = blockIdx.y;          // 0..63 m-group (8 m-tiles)
    const int ki0 = kib * 128;

    // ---- stage W hi/lo (swizzled) + bias : once per CTA ----
    {
        const int n = tid & 127, jb = (tid >> 7) * 32;
        const uint4 *wh = reinterpret_cast<const uint4 *>(g_Wh + (ki0 + n) * 64 + jb);
        const uint4 *wl = reinterpret_cast<const uint4 *>(g_Wl + (ki0 + n) * 64 + jb);
        const int n7 = n & 7;
#pragma unroll
        for (int q = 0; q < 4; ++q) {
            const int up = ((jb >> 3) + q) ^ n7;
            *reinterpret_cast<uint4 *>(smem + SM_WH + n * 128 + up * 16) = wh[q];
            *reinterpret_cast<uint4 *>(smem + SM_WL + n * 128 + up * 16) = wl[q];
        }
        if (tid < 128) reinterpret_cast<float *>(smem + SM_BIAS)[tid] = g_bias[ki0 + tid];
    }

    // lane-constant address pieces
    const int rA = lane & 15;                          // A row within 16 (+ wm*32 + ms*16)
    const uint32_t aAbase = sb + SM_X + (uint32_t)(wm * 32 + rA) * 128;
    const int rA7 = rA & 7;
    const int selA = lane >> 4;                        // +16B half select
    const int rBl = (lane & 7) + ((lane >> 4) << 3);   // B row within 16
    const uint32_t aBbase = sb + SM_WH + (uint32_t)(wn * 64 + rBl) * 128;
    const int rB7 = lane & 7;
    const int selB = (lane >> 3) & 1;

    const int mm = tid & 127, jb0 = (tid >> 7) * 32, mm7 = mm & 7;

#pragma unroll 1
    for (int t = 0; t < 8; ++t) {
        const int mt = grp * 8 + t;
        const int m0 = mt * 128;
        const float *xb = x + ((size_t)(m0 >> 14)) * (64 * (size_t)NSEQ) + (m0 & (NSEQ - 1));

        __syncthreads();   // previous epilogue readback complete (or W stage on t=0)

        // ---- stage x: LDG f32 -> bf16 hi/lo split -> swizzled STS.128 ----
#pragma unroll
        for (int q = 0; q < 4; ++q) {
            const int j0 = jb0 + q * 8;
            uint32_t hp[4], lp[4];
#pragma unroll
            for (int e = 0; e < 4; ++e) {
                float f0 = xb[(size_t)(j0 + 2 * e) * NSEQ + mm];
                float f1 = xb[(size_t)(j0 + 2 * e + 1) * NSEQ + mm];
                __nv_bfloat16 h0 = __float2bfloat16_rn(f0);
                __nv_bfloat16 h1 = __float2bfloat16_rn(f1);
                float r0 = f0 - __bfloat162float(h0);
                float r1 = f1 - __bfloat162float(h1);
                hp[e] = (uint32_t)__bfloat16_as_ushort(h0) |
                        ((uint32_t)__bfloat16_as_ushort(h1) << 16);
                lp[e] = (uint32_t)__bfloat16_as_ushort(__float2bfloat16_rn(r0)) |
                        ((uint32_t)__bfloat16_as_ushort(__float2bfloat16_rn(r1)) << 16);
            }
            const int up = (j0 >> 3) ^ mm7;
            *reinterpret_cast<uint4 *>(smem + SM_X + mm * 128 + up * 16) =
                make_uint4(hp[0], hp[1], hp[2], hp[3]);
            *reinterpret_cast<uint4 *>(smem + SM_XL + mm * 128 + up * 16) =
                make_uint4(lp[0], lp[1], lp[2], lp[3]);
        }
        __syncthreads();

        // ---- mma mainloop ----
        float acc[2][8][4];
#pragma unroll
        for (int a1 = 0; a1 < 2; ++a1)
#pragma unroll
            for (int b1 = 0; b1 < 8; ++b1)
#pragma unroll
                for (int c1 = 0; c1 < 4; ++c1) acc[a1][b1][c1] = 0.f;

#pragma unroll
        for (int ks = 0; ks < 4; ++ks) {
            uint32_t Ah[2][4], Al[2][4];
            const uint32_t uA = (uint32_t)(((ks * 2 + selA) ^ rA7) * 16);
#pragma unroll
            for (int ms = 0; ms < 2; ++ms) {
                ldsm4(Ah[ms], aAbase + ms * 2048 + uA);
                ldsm4(Al[ms], aAbase + 16384 + ms * 2048 + uA);
            }
#pragma unroll
            for (int nh = 0; nh < 2; ++nh) {
                uint32_t Bh[2][4], Bl[2][4];
                const uint32_t uB = (uint32_t)(((ks * 2 + selB) ^ rB7) * 16);
#pragma unroll
                for (int p = 0; p < 2; ++p) {
                    ldsm4(Bh[p], aBbase + nh * 4096 + p * 2048 + uB);
                    ldsm4(Bl[p], aBbase + 16384 + nh * 4096 + p * 2048 + uB);
                }
#pragma unroll
                for (int ms = 0; ms < 2; ++ms)
#pragma unroll
                    for (int ns = 0; ns < 4; ++ns) {
                        const int p = ns >> 1, o = (ns & 1) * 2;
                        float *c = acc[ms][nh * 4 + ns];
                        mma16816(c, Ah[ms], Bh[p][o], Bh[p][o + 1]);  // xh*wh
                        mma16816(c, Al[ms], Bh[p][o], Bh[p][o + 1]);  // xl*wh
                        mma16816(c, Ah[ms], Bl[p][o], Bl[p][o + 1]);  // xh*wl
                    }
            }
        }
        __syncthreads();   // all ldmatrix reads of X done before epi overwrite

        // ---- epilogue: bias + clip + shfl L1-normalize + swizzled STS ----
        {
            float2 b2[8];
#pragma unroll
            for (int n = 0; n < 8; ++n)
                b2[n] = *reinterpret_cast<const float2 *>(
                    smem + SM_BIAS + (wn * 64 + n * 8 + (lane & 3) * 2) * 4);
            const float HI = 1.0f - 1e-5f;
#pragma unroll
            for (int ms = 0; ms < 2; ++ms)
#pragma unroll
                for (int h = 0; h < 2; ++h) {
                    float s = 0.f;
#pragma unroll
                    for (int n = 0; n < 8; ++n) {
                        float v0 = fminf(fmaxf(acc[ms][n][2 * h] + b2[n].x, 1e-5f), HI);
                        float v1 = fminf(fmaxf(acc[ms][n][2 * h + 1] + b2[n].y, 1e-5f), HI);
                        acc[ms][n][2 * h] = v0;
                        acc[ms][n][2 * h + 1] = v1;
                        s += v0 + v1;
                    }
                    s += __shfl_xor_sync(0xffffffffu, s, 1);
                    s += __shfl_xor_sync(0xffffffffu, s, 2);
                    const float inv = __fdividef(1.0f, s);
                    const int row = wm * 32 + ms * 16 + (lane >> 2) + h * 8;
                    const int r5 = row & 31;
#pragma unroll
                    for (int n = 0; n < 8; ++n) {
                        const int col = wn * 64 + n * 8 + (lane & 3) * 2;
                        const int up = (col >> 2) ^ r5;
                        *reinterpret_cast<float2 *>(smem + SM_X + row * 512 + up * 16 +
                                                    (col & 3) * 4) =
                            make_float2(acc[ms][n][2 * h] * inv, acc[ms][n][2 * h + 1] * inv);
                    }
                }
        }
        __syncthreads();

        // ---- coalesced store: thread = half-row (64 f32 = 16 float4) ----
        {
            const int row = tid >> 1, hh = tid & 1;
            const int r5 = row & 31;
            float *op = out + (size_t)(m0 + row) * 4096 + ki0 + hh * 64;
#pragma unroll
            for (int c = 0; c < 16; ++c) {
                const int up = (hh * 16 + c) ^ r5;
                const float4 v =
                    *reinterpret_cast<const float4 *>(smem + SM_X + row * 512 + up * 16);
                *reinterpret_cast<float4 *>(op + c * 4) = v;
            }
        }
    }
}

// ---------------------------------------------------------------------------
extern "C" void kernel_launch(void *const *d_in, const int *in_sizes, int n_in,
                              void *d_out, int out_size) {
    const float *x  = (const float *)d_in[0];   // (4, 64, 16384) f32
    const float *cm = (const float *)d_in[1];   // (64, 64) f32
    const float *W  = (const float *)d_in[2];   // (64, 64, 128) f32
    float *out = (float *)d_out;                // (65536, 4096) f32

    (void)in_sizes; (void)n_in; (void)out_size;

    cudaFuncSetAttribute(mma_kernel, cudaFuncAttributeMaxDynamicSharedMemorySize, SM_TOTAL);
    prep_kernel<<<64, 256>>>(W, cm);
    mma_kernel<<<dim3(32, 64), 256, SM_TOTAL>>>(x, out);
}

// round 4
// speedup vs baseline: 2.8872x; 2.8872x over previous
#include <cuda_runtime.h>
#include <cuda_fp16.h>
#include <cstdint>

#define NSEQ 16384

__device__ __half g_Wh[4096 * 64];   // [ki][j] fp16 W
__device__ float  g_bias[4096];      // [ki]

// smem byte offsets
#define SM_W     0                    // [128 n][64 j] fp16 swizzled  (16384)
#define SM_BIAS  16384                // 128 f32                       (512)
#define SM_X     16896                // 2 buffers: hi 16K + lo 16K each
#define SM_XBUF  32768
#define SM_TOTAL (16896 + 2 * 32768)  // 82432

__device__ __forceinline__ uint32_t smem_u32(const void *p) {
    uint32_t a;
    asm("{ .reg .u64 t; cvta.to.shared.u64 t, %1; cvt.u32.u64 %0, t; }" : "=r"(a) : "l"(p));
    return a;
}
__device__ __forceinline__ void ldsm4(uint32_t *r, uint32_t a) {
    asm volatile("ldmatrix.sync.aligned.m8n8.x4.shared.b16 {%0,%1,%2,%3}, [%4];"
                 : "=r"(r[0]), "=r"(r[1]), "=r"(r[2]), "=r"(r[3]) : "r"(a));
}
__device__ __forceinline__ void mma16816(float *c, const uint32_t *a, uint32_t b0, uint32_t b1) {
    asm volatile("mma.sync.aligned.m16n8k16.row.col.f32.f16.f16.f32 "
                 "{%0,%1,%2,%3}, {%4,%5,%6,%7}, {%8,%9}, {%0,%1,%2,%3};"
                 : "+f"(c[0]), "+f"(c[1]), "+f"(c[2]), "+f"(c[3])
                 : "r"(a[0]), "r"(a[1]), "r"(a[2]), "r"(a[3]), "r"(b0), "r"(b1));
}

// ---------------------------------------------------------------------------
// Prep: W -> fp16 g_Wh [ki][j]; bias[ki] = cm[k] . Wcm[k][i]
// ---------------------------------------------------------------------------
__global__ void prep_kernel(const float *__restrict__ W, const float *__restrict__ cm) {
    const int k = blockIdx.x, tid = threadIdx.x;
    const float *Wk = W + k * 64 * 128;
#pragma unroll
    for (int t = 0; t < 16; ++t) {
        int e = tid + t * 256;            // (i, j)
        int i = e >> 6, j = e & 63;
        g_Wh[(k * 64 + i) * 64 + j] = __float2half_rn(Wk[i * 128 + j]);
    }
    if (tid < 64) {
        const int i = tid;
        const float *cmk = cm + k * 64;
        float s = 0.f;
#pragma unroll 8
        for (int j = 0; j < 64; ++j)
            s = fmaf(cmk[j], Wk[i * 128 + 64 + j], s);
        g_bias[k * 64 + i] = s;
    }
}

// ---------------------------------------------------------------------------
// Main: 512 threads, CTA tile 128m x 128n, K=64, 8 m-tiles per CTA.
// 16 warps as 8m x 2n (warp = 16m x 64n = one full i-group).
// fp16 2-pass split (xh*w + xl*w), fp32 accum. X double-buffered; LDG(t+1)
// issued before mma(t). Epilogue: clip + 2-shfl L1-normalize + direct STG.64.
// ---------------------------------------------------------------------------
__global__ __launch_bounds__(512, 1)
void mma_kernel(const float *__restrict__ x, float *__restrict__ out) {
    extern __shared__ char smem[];
    const uint32_t sb = smem_u32(smem);
    const int tid = threadIdx.x;
    const int lane = tid & 31, wid = tid >> 5;
    const int wm = wid & 7, wn = wid >> 3;
    const int ki0 = blockIdx.x * 128;
    const int grp = blockIdx.y;

    // ---- stage W (swizzled) + bias ----
    {
        const int n = tid & 127, c2 = tid >> 7;
        const uint4 *wsrc = reinterpret_cast<const uint4 *>(g_Wh + (ki0 + n) * 64);
        const int n7 = n & 7;
#pragma unroll
        for (int q = 0; q < 2; ++q) {
            const int ch = c2 * 2 + q;
            *reinterpret_cast<uint4 *>(smem + SM_W + n * 128 + (ch ^ n7) * 16) = wsrc[ch];
        }
        if (tid < 128) reinterpret_cast<float *>(smem + SM_BIAS)[tid] = g_bias[ki0 + tid];
    }

    const int mm = tid & 127, jh = tid >> 7, mm7 = mm & 7;

    auto ldx = [&](int t, float *xf) {
        const int m0 = (grp * 8 + t) * 128;
        const float *xb = x + ((size_t)(m0 >> 14)) * (64 * (size_t)NSEQ) + (m0 & (NSEQ - 1)) + mm;
#pragma unroll
        for (int e = 0; e < 16; ++e)
            xf[e] = xb[(size_t)(jh * 16 + e) * NSEQ];
    };
    auto stx = [&](int b, const float *xf) {
        char *base = smem + SM_X + b * SM_XBUF + mm * 128;
#pragma unroll
        for (int q = 0; q < 2; ++q) {
            uint32_t hp[4], lp[4];
#pragma unroll
            for (int e = 0; e < 4; ++e) {
                const float f0 = xf[q * 8 + 2 * e], f1 = xf[q * 8 + 2 * e + 1];
                const __half h0 = __float2half_rn(f0), h1 = __float2half_rn(f1);
                const __half l0 = __float2half_rn(f0 - __half2float(h0));
                const __half l1 = __float2half_rn(f1 - __half2float(h1));
                hp[e] = (uint32_t)__half_as_ushort(h0) | ((uint32_t)__half_as_ushort(h1) << 16);
                lp[e] = (uint32_t)__half_as_ushort(l0) | ((uint32_t)__half_as_ushort(l1) << 16);
            }
            const int up = ((jh * 2 + q) ^ mm7) * 16;
            *reinterpret_cast<uint4 *>(base + up) = make_uint4(hp[0], hp[1], hp[2], hp[3]);
            *reinterpret_cast<uint4 *>(base + 16384 + up) = make_uint4(lp[0], lp[1], lp[2], lp[3]);
        }
    };

    // lane-constant ldmatrix addressing
    const uint32_t aA0 = sb + SM_X + (uint32_t)(wm * 16 + (lane & 15)) * 128;
    const int selA = lane >> 4;
    const int rBl = (lane & 7) + ((lane >> 4) << 3);
    const uint32_t aB0 = sb + SM_W + (uint32_t)(wn * 64 + rBl) * 128;
    const int selB = (lane >> 3) & 1;
    const int l7 = lane & 7;

    // prologue: stage X[0]
    float xf[16];
    ldx(0, xf);
    stx(0, xf);
    __syncthreads();

    // bias fragments (after sync)
    float2 b2[8];
#pragma unroll
    for (int nf = 0; nf < 8; ++nf)
        b2[nf] = *reinterpret_cast<const float2 *>(
            smem + SM_BIAS + (wn * 64 + nf * 8 + (lane & 3) * 2) * 4);

    const float HI = 1.0f - 1e-5f;

#pragma unroll 1
    for (int t = 0; t < 8; ++t) {
        const int b = t & 1;
        if (t < 7) ldx(t + 1, xf);       // overlap gmem with mma below

        float acc[8][4];
#pragma unroll
        for (int nf = 0; nf < 8; ++nf)
#pragma unroll
            for (int c = 0; c < 4; ++c) acc[nf][c] = 0.f;

        const uint32_t aA = aA0 + (uint32_t)b * SM_XBUF;
#pragma unroll
        for (int ks = 0; ks < 4; ++ks) {
            uint32_t Ah[4], Al[4];
            const uint32_t uA = (uint32_t)(((ks * 2 + selA) ^ l7) * 16);
            ldsm4(Ah, aA + uA);
            ldsm4(Al, aA + 16384 + uA);
            const uint32_t uB = (uint32_t)(((ks * 2 + selB) ^ l7) * 16);
#pragma unroll
            for (int p = 0; p < 4; ++p) {
                uint32_t Bf[4];
                ldsm4(Bf, aB0 + p * 2048 + uB);
                mma16816(acc[2 * p],     Ah, Bf[0], Bf[1]);
                mma16816(acc[2 * p],     Al, Bf[0], Bf[1]);
                mma16816(acc[2 * p + 1], Ah, Bf[2], Bf[3]);
                mma16816(acc[2 * p + 1], Al, Bf[2], Bf[3]);
            }
        }

        if (t < 7) stx((t + 1) & 1, xf); // fill other buffer

        // ---- epilogue: bias + clip + L1-normalize + direct store ----
        const int m0 = (grp * 8 + t) * 128;
#pragma unroll
        for (int h = 0; h < 2; ++h) {
            float v[8][2];
            float s = 0.f;
#pragma unroll
            for (int nf = 0; nf < 8; ++nf) {
                const float v0 = fminf(fmaxf(acc[nf][2 * h]     + b2[nf].x, 1e-5f), HI);
                const float v1 = fminf(fmaxf(acc[nf][2 * h + 1] + b2[nf].y, 1e-5f), HI);
                v[nf][0] = v0; v[nf][1] = v1;
                s += v0 + v1;
            }
            s += __shfl_xor_sync(0xffffffffu, s, 1);
            s += __shfl_xor_sync(0xffffffffu, s, 2);
            const float inv = __fdividef(1.0f, s);
            const int row = wm * 16 + (lane >> 2) + h * 8;
            float *op = out + (size_t)(m0 + row) * 4096 + ki0 + wn * 64 + (lane & 3) * 2;
#pragma unroll
            for (int nf = 0; nf < 8; ++nf)
                *reinterpret_cast<float2 *>(op + nf * 8) =
                    make_float2(v[nf][0] * inv, v[nf][1] * inv);
        }

        if (t < 7) __syncthreads();
    }
}

// ---------------------------------------------------------------------------
extern "C" void kernel_launch(void *const *d_in, const int *in_sizes, int n_in,
                              void *d_out, int out_size) {
    const float *x  = (const float *)d_in[0];   // (4, 64, 16384) f32
    const float *cm = (const float *)d_in[1];   // (64, 64) f32
    const float *W  = (const float *)d_in[2];   // (64, 64, 128) f32
    float *out = (float *)d_out;                // (65536, 4096) f32

    (void)in_sizes; (void)n_in; (void)out_size;

    cudaFuncSetAttribute(mma_kernel, cudaFuncAttributeMaxDynamicSharedMemorySize, SM_TOTAL);
    prep_kernel<<<64, 256>>>(W, cm);
    mma_kernel<<<dim3(32, 64), 512, SM_TOTAL>>>(x, out);
}